// round 3
// baseline (speedup 1.0000x reference)
#include <cuda_runtime.h>
#include <cstddef>
#include <cstdint>

#define NPTS 1000000
#define KSZ 9
#define EPSBN 1e-5f
#define NF4 (NPTS * 16 / 4)
#define CONVGRID 15625            // 64 points per block, exact: 15625*64 = 1M
#define MIDB 64
#define RPB 245                   // ceil(15625/64)
#define SGRID 1184
#define SSTRIDE (SGRID * 256)

typedef unsigned long long ull;

// ---------------- scratch (device globals: no allocation) ----------------
__device__ float g_h[(size_t)NPTS * 16];           // conv1 raw output, 64 MB
__device__ float4 g_part4[CONVGRID * 8];           // per-block stats partials
__device__ float g_mid[MIDB * 32];
__device__ __align__(16) float g_st1[32];          // BN1 scale[16], shift[16]
__device__ __align__(16) float g_st2[32];          // BN2 scale[16], shift[16]

// ---------------- f32x2 packed helpers ----------------
__device__ __forceinline__ ull pack2(float lo, float hi) {
    ull r; asm("mov.b64 %0, {%1, %2};" : "=l"(r) : "f"(lo), "f"(hi)); return r;
}
__device__ __forceinline__ void unpack2(ull v, float& lo, float& hi) {
    asm("mov.b64 {%0, %1}, %2;" : "=f"(lo), "=f"(hi) : "l"(v));
}
__device__ __forceinline__ ull fma2(ull a, ull b, ull c) {
    ull d; asm("fma.rn.f32x2 %0, %1, %2, %3;" : "=l"(d) : "l"(a), "l"(b), "l"(c)); return d;
}
__device__ __forceinline__ ull add2(ull a, ull b) {
    ull d; asm("add.rn.f32x2 %0, %1, %2;" : "=l"(d) : "l"(a), "l"(b)); return d;
}

#define BNAPP(v, s, h) { v = fmaf(v, s, h); v = fmaxf(v, 0.2f * v); }

// =====================================================================
// Fused tree-conv, 4 lanes per point-column, 4 points per thread.
//  - gather: 4-lane groups load 16B chunks of each 64B row (coalesced)
//  - weights: pre-duplicated (w,w) f32x2 pairs in smem, bank-skewed per g
//  - math: fma.rn.f32x2, point-pairs packed in one 64-bit accumulator
//  - per-block BN stats (sum, sumsq per channel) fused at the end
// =====================================================================
template <bool BN, bool BIAS>
__global__ void __launch_bounds__(64) conv_kernel(
    const float* __restrict__ src, const int* __restrict__ ind,
    const float* __restrict__ w, const float* __restrict__ bias,
    float* __restrict__ dst)
{
    // wdup[g][j][cc][o] : (w,w) pairs. g-stride 580 ull (4640B) => the 4
    // per-warp group addresses land on banks 0-3 / 8-11 / 16-19 / 24-27.
    __shared__ __align__(16) ull wdup[4 * 580];    // 18560 B
    const int tid = threadIdx.x;
    const int g = tid & 3;
    const int grp = tid >> 2;

    // stage duplicated weights: w[c][o][j] with c = 4g + cc
    for (int i = tid; i < 16 * 16 * KSZ; i += 64) {
        int c = i / (16 * KSZ);
        int rem = i - c * (16 * KSZ);
        int o = rem / KSZ;
        int j = rem - o * KSZ;
        float wv = w[i];
        wdup[(c >> 2) * 580 + j * 64 + (c & 3) * 16 + o] = pack2(wv, wv);
    }
    __syncthreads();

    float4 bsc, bsh;
    if (BN) {
        bsc = reinterpret_cast<const float4*>(g_st1)[g];
        bsh = reinterpret_cast<const float4*>(g_st1 + 16)[g];
    }

    const int pbase = blockIdx.x * 64 + grp;           // points: pbase + 16*k
    const size_t ibase = (size_t)pbase * KSZ;          // ind offset: + 144*k + j

    ull acc[2][16];
#pragma unroll
    for (int pr = 0; pr < 2; pr++)
#pragma unroll
        for (int o = 0; o < 16; o++) acc[pr][o] = 0ull;

    const float4* sp = reinterpret_cast<const float4*>(src);
    const ull* wg = wdup + g * 580;

#pragma unroll
    for (int j = 0; j < KSZ; j++) {
        const int r0 = __ldg(ind + ibase + j);
        const int r1 = __ldg(ind + ibase + 144 + j);
        const int r2 = __ldg(ind + ibase + 288 + j);
        const int r3 = __ldg(ind + ibase + 432 + j);
        float4 a0 = __ldg(sp + (size_t)r0 * 4 + g);
        float4 a1 = __ldg(sp + (size_t)r1 * 4 + g);
        float4 a2 = __ldg(sp + (size_t)r2 * 4 + g);
        float4 a3 = __ldg(sp + (size_t)r3 * 4 + g);
        if (BN) {
            BNAPP(a0.x, bsc.x, bsh.x); BNAPP(a0.y, bsc.y, bsh.y);
            BNAPP(a0.z, bsc.z, bsh.z); BNAPP(a0.w, bsc.w, bsh.w);
            BNAPP(a1.x, bsc.x, bsh.x); BNAPP(a1.y, bsc.y, bsh.y);
            BNAPP(a1.z, bsc.z, bsh.z); BNAPP(a1.w, bsc.w, bsh.w);
            BNAPP(a2.x, bsc.x, bsh.x); BNAPP(a2.y, bsc.y, bsh.y);
            BNAPP(a2.z, bsc.z, bsh.z); BNAPP(a2.w, bsc.w, bsh.w);
            BNAPP(a3.x, bsc.x, bsh.x); BNAPP(a3.y, bsc.y, bsh.y);
            BNAPP(a3.z, bsc.z, bsh.z); BNAPP(a3.w, bsc.w, bsh.w);
        }
        ull vp0[4], vp1[4];
        vp0[0] = pack2(a0.x, a1.x); vp0[1] = pack2(a0.y, a1.y);
        vp0[2] = pack2(a0.z, a1.z); vp0[3] = pack2(a0.w, a1.w);
        vp1[0] = pack2(a2.x, a3.x); vp1[1] = pack2(a2.y, a3.y);
        vp1[2] = pack2(a2.z, a3.z); vp1[3] = pack2(a2.w, a3.w);

        const ulonglong2* wj = reinterpret_cast<const ulonglong2*>(wg + j * 64);
#pragma unroll
        for (int cc = 0; cc < 4; cc++) {
            const ull v0 = vp0[cc];
            const ull v1 = vp1[cc];
#pragma unroll
            for (int o2 = 0; o2 < 8; o2++) {
                ulonglong2 ww = wj[cc * 8 + o2];
                acc[0][o2 * 2]     = fma2(v0, ww.x, acc[0][o2 * 2]);
                acc[1][o2 * 2]     = fma2(v1, ww.x, acc[1][o2 * 2]);
                acc[0][o2 * 2 + 1] = fma2(v0, ww.y, acc[0][o2 * 2 + 1]);
                acc[1][o2 * 2 + 1] = fma2(v1, ww.y, acc[1][o2 * 2 + 1]);
            }
        }
    }

    // reduce-scatter over the 4-lane group (packed pairs move together)
    float4 s4 = make_float4(0.f, 0.f, 0.f, 0.f);
    float4 q4 = make_float4(0.f, 0.f, 0.f, 0.f);
    float4 b4;
    if (BIAS) b4 = reinterpret_cast<const float4*>(bias)[g];

#pragma unroll
    for (int pr = 0; pr < 2; pr++) {
        ull h8[8];
#pragma unroll
        for (int i = 0; i < 8; i++) {
            ull a = acc[pr][i], b = acc[pr][i + 8];
            ull mine = (g & 2) ? a : b;
            ull oth = __shfl_xor_sync(0xffffffffu, mine, 2);
            h8[i] = add2((g & 2) ? b : a, oth);
        }
        ull q[4];
#pragma unroll
        for (int i = 0; i < 4; i++) {
            ull a = h8[i], b = h8[i + 4];
            ull mine = (g & 1) ? a : b;
            ull oth = __shfl_xor_sync(0xffffffffu, mine, 1);
            q[i] = add2((g & 1) ? b : a, oth);
        }
        float lo[4], hi[4];
#pragma unroll
        for (int i = 0; i < 4; i++) unpack2(q[i], lo[i], hi[i]);
        if (BIAS) {
            lo[0] += b4.x; lo[1] += b4.y; lo[2] += b4.z; lo[3] += b4.w;
            hi[0] += b4.x; hi[1] += b4.y; hi[2] += b4.z; hi[3] += b4.w;
        }
        const int plo = pbase + 16 * (2 * pr);
        const int phi = pbase + 16 * (2 * pr + 1);
        reinterpret_cast<float4*>(dst)[(size_t)plo * 4 + g] =
            make_float4(lo[0], lo[1], lo[2], lo[3]);
        reinterpret_cast<float4*>(dst)[(size_t)phi * 4 + g] =
            make_float4(hi[0], hi[1], hi[2], hi[3]);
        s4.x += lo[0] + hi[0]; s4.y += lo[1] + hi[1];
        s4.z += lo[2] + hi[2]; s4.w += lo[3] + hi[3];
        q4.x += lo[0] * lo[0] + hi[0] * hi[0];
        q4.y += lo[1] * lo[1] + hi[1] * hi[1];
        q4.z += lo[2] * lo[2] + hi[2] * hi[2];
        q4.w += lo[3] * lo[3] + hi[3] * hi[3];
    }

    // ---- fused per-block BN stats (deterministic), reuse weight smem ----
    __syncthreads();
    float4* s1 = reinterpret_cast<float4*>(wdup);       // 64 float4
    float4* s2 = s1 + 64;
    s1[tid] = s4; s2[tid] = q4;
    __syncthreads();
#pragma unroll
    for (int off = 32; off >= 4; off >>= 1) {
        if (tid < off) {
            float4 a = s1[tid], b = s1[tid + off];
            a.x += b.x; a.y += b.y; a.z += b.z; a.w += b.w; s1[tid] = a;
            float4 c = s2[tid], d = s2[tid + off];
            c.x += d.x; c.y += d.y; c.z += d.z; c.w += d.w; s2[tid] = c;
        }
        __syncthreads();
    }
    if (tid < 4) {
        g_part4[blockIdx.x * 8 + tid] = s1[tid];
        g_part4[blockIdx.x * 8 + 4 + tid] = s2[tid];
    }
}

// ---------------- mid-stage stats reduction: 15625 -> 64 partials ----------------
__global__ __launch_bounds__(256) void midstats_kernel()
{
    const float* part = reinterpret_cast<const float*>(g_part4);
    const int tid = threadIdx.x;
    const int v = tid & 31;
    const int lane = tid >> 5;
    const int r0 = blockIdx.x * RPB;
    const int rend = min(r0 + RPB, CONVGRID);
    float loc = 0.f;
    for (int r = r0 + lane; r < rend; r += 8) loc += part[r * 32 + v];
    __shared__ float sm[256];
    sm[tid] = loc;
    __syncthreads();
    if (tid < 32) {
        float t = 0.f;
#pragma unroll
        for (int k = 0; k < 8; k++) t += sm[tid + k * 32];
        g_mid[blockIdx.x * 32 + tid] = t;
    }
}

// ---------------- finalize: 64 partials -> BN scale/shift ----------------
template <int S>
__global__ void finalize_kernel(const float* __restrict__ gamma,
                                const float* __restrict__ beta)
{
    const int tid = threadIdx.x;   // 32 threads
    __shared__ float sm[32];
    float t = 0.f;
    for (int r = 0; r < MIDB; r++) t += g_mid[r * 32 + tid];
    sm[tid] = t;
    __syncthreads();
    if (tid < 16) {
        const float inv_n = 1.0f / (float)NPTS;
        float mean = sm[tid] * inv_n;
        float var = sm[16 + tid] * inv_n - mean * mean;
        float rstd = rsqrtf(var + EPSBN);
        float sc = gamma[tid] * rstd;
        float sh = beta[tid] - mean * sc;
        float* st = (S == 1) ? g_st1 : g_st2;
        st[tid] = sc;
        st[16 + tid] = sh;
    }
}

// ---------- epilogue: out = leaky(BN2(raw2) + data), in place on d_out ----------
__global__ __launch_bounds__(256) void bnres_kernel(
    const float* __restrict__ data, float* __restrict__ out)
{
    const int tid = threadIdx.x;
    const int idx = blockIdx.x * 256 + tid;
    const int g = tid & 3;
    float4 sc = reinterpret_cast<const float4*>(g_st2)[g];
    float4 sh = reinterpret_cast<const float4*>(g_st2 + 16)[g];
    const float4* dd = reinterpret_cast<const float4*>(data);
    float4* oo = reinterpret_cast<float4*>(out);
    for (int i = idx; i < NF4; i += SSTRIDE) {
        float4 r = oo[i];
        float4 d = dd[i];
        float4 y;
        y.x = fmaf(r.x, sc.x, sh.x) + d.x;
        y.y = fmaf(r.y, sc.y, sh.y) + d.y;
        y.z = fmaf(r.z, sc.z, sh.z) + d.z;
        y.w = fmaf(r.w, sc.w, sh.w) + d.w;
        y.x = fmaxf(y.x, 0.2f * y.x);
        y.y = fmaxf(y.y, 0.2f * y.y);
        y.z = fmaxf(y.z, 0.2f * y.z);
        y.w = fmaxf(y.w, 0.2f * y.w);
        oo[i] = y;
    }
}

extern "C" void kernel_launch(void* const* d_in, const int* in_sizes, int n_in,
                              void* d_out, int out_size)
{
    const float* data   = (const float*)d_in[0];
    const int*   ind    = (const int*)  d_in[1];
    const float* w1     = (const float*)d_in[2];
    const float* b1     = (const float*)d_in[3];
    const float* gamma1 = (const float*)d_in[4];
    const float* beta1  = (const float*)d_in[5];
    const float* w2     = (const float*)d_in[6];
    const float* gamma2 = (const float*)d_in[7];
    const float* beta2  = (const float*)d_in[8];
    float* out = (float*)d_out;

    float* gh;
    cudaGetSymbolAddress((void**)&gh, g_h);

    conv_kernel<false, true><<<CONVGRID, 64>>>(data, ind, w1, b1, gh);
    midstats_kernel<<<MIDB, 256>>>();
    finalize_kernel<1><<<1, 32>>>(gamma1, beta1);
    conv_kernel<true, false><<<CONVGRID, 64>>>(gh, ind, w2, nullptr, out);
    midstats_kernel<<<MIDB, 256>>>();
    finalize_kernel<2><<<1, 32>>>(gamma2, beta2);
    bnres_kernel<<<SGRID, 256>>>(data, out);
}

// round 4
// speedup vs baseline: 1.9643x; 1.9643x over previous
#include <cuda_runtime.h>
#include <cstddef>
#include <cstdint>

#define NPTS 1000000
#define KSZ 9
#define EPSBN 1e-5f
#define NF4 (NPTS * 16 / 4)
#define CONVGRID 3907             // 256 points per block (last block partial)
#define MIDB 64
#define RPB ((CONVGRID + MIDB - 1) / MIDB)
#define SGRID 1184
#define SSTRIDE (SGRID * 256)

typedef unsigned long long ull;

// ---------------- scratch (device globals: no allocation) ----------------
__device__ float g_h[(size_t)NPTS * 16];           // conv1 raw output, 64 MB
__device__ float4 g_part4[CONVGRID * 8];           // per-block stats partials
__device__ float g_mid[MIDB * 32];
__device__ __align__(16) float g_st1[32];          // BN1 scale[16], shift[16]
__device__ __align__(16) float g_st2[32];          // BN2 scale[16], shift[16]

// ---------------- f32x2 packed helpers ----------------
__device__ __forceinline__ ull pack2(float lo, float hi) {
    ull r; asm("mov.b64 %0, {%1, %2};" : "=l"(r) : "f"(lo), "f"(hi)); return r;
}
__device__ __forceinline__ void unpack2(ull v, float& lo, float& hi) {
    asm("mov.b64 {%0, %1}, %2;" : "=f"(lo), "=f"(hi) : "l"(v));
}
__device__ __forceinline__ ull fma2(ull a, ull b, ull c) {
    ull d; asm("fma.rn.f32x2 %0, %1, %2, %3;" : "=l"(d) : "l"(a), "l"(b), "l"(c)); return d;
}
__device__ __forceinline__ ull add2(ull a, ull b) {
    ull d; asm("add.rn.f32x2 %0, %1, %2;" : "=l"(d) : "l"(a), "l"(b)); return d;
}

#define BNAPP(v, s, h) { v = fmaf(v, s, h); v = fmaxf(v, 0.2f * v); }

// =====================================================================
// Fused tree-conv.
//  - 4 lanes per point-column (lane g owns input channels 4g..4g+3)
//  - 4 points per thread (n = pbase + G + 64k) -> weight LDS amortized 4x
//  - weights NOT duplicated: f32x2 packs output-channel pairs; the value
//    is duplicated in-register ((v,v)), weights load straight from smem
//  - coalesced gather: one LDG.128 per lane = 16B chunk of a 64B row
//  - reduce-scatter over the 4-lane group -> lane g holds o=4g..4g+3
//  - per-block BN stats (sum, sumsq per channel) fused at the end
// =====================================================================
template <bool BN, bool BIAS>
__global__ void __launch_bounds__(256) conv_kernel(
    const float* __restrict__ src, const int* __restrict__ ind,
    const float* __restrict__ w, const float* __restrict__ bias,
    float* __restrict__ dst)
{
    // ws[g][j][cc][o]: g-stride 580 floats (2320B = 145*16, 16B aligned;
    // 580 mod 32 = 4 -> the 4 per-warp group addresses hit disjoint banks).
    // Reused afterwards for the 8KB stats reduction (2320 floats >= 2048).
    __shared__ __align__(16) float ws[4 * 580];
    const int tid = threadIdx.x;
    const int g = tid & 3;
    const int G = tid >> 2;

    // stage weights: w[c][o][j] (c*144 + o*9 + j), c = 4g + cc
    for (int i = tid; i < 16 * 16 * KSZ; i += 256) {
        int c = i / 144;
        int rem = i - c * 144;
        int o = rem / 9;
        int j = rem - o * 9;
        ws[(c >> 2) * 580 + j * 64 + (c & 3) * 16 + o] = w[i];
    }
    __syncthreads();

    float4 bsc, bsh;
    if (BN) {
        bsc = reinterpret_cast<const float4*>(g_st1)[g];
        bsh = reinterpret_cast<const float4*>(g_st1 + 16)[g];
    }

    const int pbase = blockIdx.x * 256;
    int npt[4]; bool vld[4];
#pragma unroll
    for (int k = 0; k < 4; k++) {
        npt[k] = pbase + G + 64 * k;
        vld[k] = npt[k] < NPTS;
    }

    ull acc[4][8];
#pragma unroll
    for (int k = 0; k < 4; k++)
#pragma unroll
        for (int p = 0; p < 8; p++) acc[k][p] = 0ull;

    const float4* sp = reinterpret_cast<const float4*>(src);
    const float* wg = ws + g * 580;

#pragma unroll
    for (int j = 0; j < KSZ; j++) {
        float4 a[4];
#pragma unroll
        for (int k = 0; k < 4; k++) {
            if (vld[k]) {
                int rk = __ldg(ind + npt[k] * KSZ + j);
                a[k] = __ldg(sp + (size_t)rk * 4 + g);
            } else {
                a[k] = make_float4(0.f, 0.f, 0.f, 0.f);
            }
            if (BN) {
                BNAPP(a[k].x, bsc.x, bsh.x); BNAPP(a[k].y, bsc.y, bsh.y);
                BNAPP(a[k].z, bsc.z, bsh.z); BNAPP(a[k].w, bsc.w, bsh.w);
            }
        }
        const ulonglong2* wj = reinterpret_cast<const ulonglong2*>(wg + j * 64);
#pragma unroll
        for (int cc = 0; cc < 4; cc++) {
            // 16 weight floats (o0..15) = 8 f32x2 pairs, shared by 4 points
            ulonglong2 w0 = wj[cc * 4 + 0];
            ulonglong2 w1 = wj[cc * 4 + 1];
            ulonglong2 w2 = wj[cc * 4 + 2];
            ulonglong2 w3 = wj[cc * 4 + 3];
#pragma unroll
            for (int k = 0; k < 4; k++) {
                const float v = (cc == 0) ? a[k].x : (cc == 1) ? a[k].y
                              : (cc == 2) ? a[k].z : a[k].w;
                const ull v2 = pack2(v, v);
                acc[k][0] = fma2(v2, w0.x, acc[k][0]);
                acc[k][1] = fma2(v2, w0.y, acc[k][1]);
                acc[k][2] = fma2(v2, w1.x, acc[k][2]);
                acc[k][3] = fma2(v2, w1.y, acc[k][3]);
                acc[k][4] = fma2(v2, w2.x, acc[k][4]);
                acc[k][5] = fma2(v2, w2.y, acc[k][5]);
                acc[k][6] = fma2(v2, w3.x, acc[k][6]);
                acc[k][7] = fma2(v2, w3.y, acc[k][7]);
            }
        }
    }

    // reduce-scatter per point; accumulate block stats
    float4 s4 = make_float4(0.f, 0.f, 0.f, 0.f);
    float4 q4 = make_float4(0.f, 0.f, 0.f, 0.f);
    float4 b4;
    if (BIAS) b4 = reinterpret_cast<const float4*>(bias)[g];

#pragma unroll
    for (int k = 0; k < 4; k++) {
        // stage A (xor 2): pairs 0..3 = o0..7 stay with g<2; 4..7 with g>=2
        ull h4[4];
#pragma unroll
        for (int i = 0; i < 4; i++) {
            ull aa = acc[k][i], bb = acc[k][i + 4];
            ull mine = (g & 2) ? aa : bb;
            ull oth = __shfl_xor_sync(0xffffffffu, mine, 2);
            h4[i] = add2((g & 2) ? bb : aa, oth);
        }
        // stage B (xor 1): even g keeps lower 2 pairs of its half
        ull q2[2];
#pragma unroll
        for (int i = 0; i < 2; i++) {
            ull aa = h4[i], bb = h4[i + 2];
            ull mine = (g & 1) ? aa : bb;
            ull oth = __shfl_xor_sync(0xffffffffu, mine, 1);
            q2[i] = add2((g & 1) ? bb : aa, oth);
        }
        float o0, o1, o2, o3;
        unpack2(q2[0], o0, o1);
        unpack2(q2[1], o2, o3);
        if (BIAS) { o0 += b4.x; o1 += b4.y; o2 += b4.z; o3 += b4.w; }
        if (vld[k]) {
            reinterpret_cast<float4*>(dst)[(size_t)npt[k] * 4 + g] =
                make_float4(o0, o1, o2, o3);
            s4.x += o0; s4.y += o1; s4.z += o2; s4.w += o3;
            q4.x += o0 * o0; q4.y += o1 * o1; q4.z += o2 * o2; q4.w += o3 * o3;
        }
    }

    // ---- fused per-block BN stats (deterministic), reuse weight smem ----
    __syncthreads();
    float4* s1 = reinterpret_cast<float4*>(ws);        // 256 float4
    float4* s2 = s1 + 256;
    s1[tid] = s4; s2[tid] = q4;
    __syncthreads();
#pragma unroll
    for (int off = 128; off >= 4; off >>= 1) {
        if (tid < off) {
            float4 a = s1[tid], b = s1[tid + off];
            a.x += b.x; a.y += b.y; a.z += b.z; a.w += b.w; s1[tid] = a;
            float4 c = s2[tid], d = s2[tid + off];
            c.x += d.x; c.y += d.y; c.z += d.z; c.w += d.w; s2[tid] = c;
        }
        __syncthreads();
    }
    if (tid < 4) {
        g_part4[blockIdx.x * 8 + tid] = s1[tid];
        g_part4[blockIdx.x * 8 + 4 + tid] = s2[tid];
    }
}

// ---------------- mid-stage stats reduction: CONVGRID -> 64 partials ----------------
__global__ __launch_bounds__(256) void midstats_kernel()
{
    const float* part = reinterpret_cast<const float*>(g_part4);
    const int tid = threadIdx.x;
    const int v = tid & 31;
    const int lane = tid >> 5;
    const int r0 = blockIdx.x * RPB;
    const int rend = min(r0 + RPB, CONVGRID);
    float loc = 0.f;
    for (int r = r0 + lane; r < rend; r += 8) loc += part[r * 32 + v];
    __shared__ float sm[256];
    sm[tid] = loc;
    __syncthreads();
    if (tid < 32) {
        float t = 0.f;
#pragma unroll
        for (int k = 0; k < 8; k++) t += sm[tid + k * 32];
        g_mid[blockIdx.x * 32 + tid] = t;
    }
}

// ---------------- finalize: 64 partials -> BN scale/shift ----------------
template <int S>
__global__ void finalize_kernel(const float* __restrict__ gamma,
                                const float* __restrict__ beta)
{
    const int tid = threadIdx.x;   // 32 threads
    __shared__ float sm[32];
    float t = 0.f;
    for (int r = 0; r < MIDB; r++) t += g_mid[r * 32 + tid];
    sm[tid] = t;
    __syncthreads();
    if (tid < 16) {
        const float inv_n = 1.0f / (float)NPTS;
        float mean = sm[tid] * inv_n;
        float var = sm[16 + tid] * inv_n - mean * mean;
        float rstd = rsqrtf(var + EPSBN);
        float sc = gamma[tid] * rstd;
        float sh = beta[tid] - mean * sc;
        float* st = (S == 1) ? g_st1 : g_st2;
        st[tid] = sc;
        st[16 + tid] = sh;
    }
}

// ---------- epilogue: out = leaky(BN2(raw2) + data), in place on d_out ----------
__global__ __launch_bounds__(256) void bnres_kernel(
    const float* __restrict__ data, float* __restrict__ out)
{
    const int tid = threadIdx.x;
    const int idx = blockIdx.x * 256 + tid;
    const int g = tid & 3;
    float4 sc = reinterpret_cast<const float4*>(g_st2)[g];
    float4 sh = reinterpret_cast<const float4*>(g_st2 + 16)[g];
    const float4* dd = reinterpret_cast<const float4*>(data);
    float4* oo = reinterpret_cast<float4*>(out);
    for (int i = idx; i < NF4; i += SSTRIDE) {
        float4 r = oo[i];
        float4 d = dd[i];
        float4 y;
        y.x = fmaf(r.x, sc.x, sh.x) + d.x;
        y.y = fmaf(r.y, sc.y, sh.y) + d.y;
        y.z = fmaf(r.z, sc.z, sh.z) + d.z;
        y.w = fmaf(r.w, sc.w, sh.w) + d.w;
        y.x = fmaxf(y.x, 0.2f * y.x);
        y.y = fmaxf(y.y, 0.2f * y.y);
        y.z = fmaxf(y.z, 0.2f * y.z);
        y.w = fmaxf(y.w, 0.2f * y.w);
        oo[i] = y;
    }
}

extern "C" void kernel_launch(void* const* d_in, const int* in_sizes, int n_in,
                              void* d_out, int out_size)
{
    const float* data   = (const float*)d_in[0];
    const int*   ind    = (const int*)  d_in[1];
    const float* w1     = (const float*)d_in[2];
    const float* b1     = (const float*)d_in[3];
    const float* gamma1 = (const float*)d_in[4];
    const float* beta1  = (const float*)d_in[5];
    const float* w2     = (const float*)d_in[6];
    const float* gamma2 = (const float*)d_in[7];
    const float* beta2  = (const float*)d_in[8];
    float* out = (float*)d_out;

    float* gh;
    cudaGetSymbolAddress((void**)&gh, g_h);

    conv_kernel<false, true><<<CONVGRID, 256>>>(data, ind, w1, b1, gh);
    midstats_kernel<<<MIDB, 256>>>();
    finalize_kernel<1><<<1, 32>>>(gamma1, beta1);
    conv_kernel<true, false><<<CONVGRID, 256>>>(gh, ind, w2, nullptr, out);
    midstats_kernel<<<MIDB, 256>>>();
    finalize_kernel<2><<<1, 32>>>(gamma2, beta2);
    bnres_kernel<<<SGRID, 256>>>(data, out);
}